// round 16
// baseline (speedup 1.0000x reference)
#include <cuda_runtime.h>
#include <cuda_bf16.h>
#include <cstdint>

// Problem constants (fixed by the dataset)
#define BB   8192
#define DIN  1024
#define NC   256       // padded gating columns (120 z + 128 a + 8 pad)
#define NE   16

// ---------------- scratch (no allocation allowed) ----------------
__device__ uint32_t g_Bh[DIN * NC / 2];   // W hi-split, [k][n] bf16, packed 2/word
__device__ uint32_t g_Bl[DIN * NC / 2];   // W lo-split
__device__ float    g_mid[BB * NC];       // gating result [b][c] (pre-bias)
__device__ float    g_w  [BB * NE];       // final expert weights [b][n]

#define CPA16(dst, src) \
    asm volatile("cp.async.ca.shared.global [%0], [%1], 16;\n" :: "r"(dst), "l"(src))

#define LDSM4(r, addr) \
    asm volatile("ldmatrix.sync.aligned.m8n8.x4.shared.b16 {%0,%1,%2,%3}, [%4];" \
        : "=r"((r)[0]), "=r"((r)[1]), "=r"((r)[2]), "=r"((r)[3]) : "r"(addr))

#define LDSM4T(r, addr) \
    asm volatile("ldmatrix.sync.aligned.m8n8.x4.trans.shared.b16 {%0,%1,%2,%3}, [%4];" \
        : "=r"((r)[0]), "=r"((r)[1]), "=r"((r)[2]), "=r"((r)[3]) : "r"(addr))

#define MMA_BF16(c, a, b0, b1) \
    asm volatile("mma.sync.aligned.m16n8k16.row.col.f32.bf16.bf16.f32 " \
        "{%0,%1,%2,%3}, {%4,%5,%6,%7}, {%8,%9}, {%0,%1,%2,%3};" \
        : "+f"((c)[0]), "+f"((c)[1]), "+f"((c)[2]), "+f"((c)[3]) \
        : "r"((a)[0]), "r"((a)[1]), "r"((a)[2]), "r"((a)[3]), "r"(b0), "r"(b1))

__device__ __forceinline__ uint32_t pack_bf2(float a, float b) {
    __nv_bfloat162 h = __floats2bfloat162_rn(a, b);
    return *(uint32_t*)&h;
}

// ---------------- kernel 0: pack + hi/lo split gating weights ----------------
__global__ void prepack_w(const float* __restrict__ Wz, const float* __restrict__ Ww) {
    // Release gemm immediately: its pre-wait portion only reads x (an input).
    asm volatile("griddepcontrol.launch_dependents;");
    int k  = blockIdx.x;      // 0..1023
    int n2 = threadIdx.x;     // 0..127 -> cols 2*n2, 2*n2+1
    float v[2];
#pragma unroll
    for (int j = 0; j < 2; j++) {
        int c = 2 * n2 + j;
        float val = 0.0f;
        if (c < 120)       val = Wz[(c >> 3) * (DIN * 8) + k * 8 + (c & 7)];
        else if (c < 248)  { int cc = c - 120; val = Ww[(cc >> 3) * (DIN * 8) + k * 8 + (cc & 7)]; }
        v[j] = val;
    }
    float h0 = __bfloat162float(__float2bfloat16(v[0]));
    float h1 = __bfloat162float(__float2bfloat16(v[1]));
    g_Bh[k * 128 + n2] = pack_bf2(h0, h1);
    g_Bl[k * 128 + n2] = pack_bf2(v[0] - h0, v[1] - h1);
}

// ---------------- kernel 1: gating GEMM via mma.sync bf16, 3-pass hi/lo ----------------
// CTA tile 128 m x 64 n (256 CTAs -> ~2 CTAs/SM co-resident, 4 warps/SMSP to hide
// LDSM->MMA stalls). K chunk 32, 32 chunks. x read fp32, hi/lo split in-kernel.
// 8 warps as 4(m) x 2(n): warp tile 32m x 32n, acc[2][4][4] = 32 regs.
#define BKC      32
#define NCHUNK   (DIN / BKC)
#define A_HL     10240            // 128 * 80
#define A_STAGE  20480
#define B_HL     4096             // 32 k * 128 B
#define B_STAGE  8192
#define SMEM_B0  (2 * A_STAGE)    // 40960
#define SMEM_TOT (2 * A_STAGE + 2 * B_STAGE)   // 57344

__global__ __launch_bounds__(256, 2) void gemm_mma(const float* __restrict__ x) {
    extern __shared__ char smraw[];
    const uint32_t smem = (uint32_t)__cvta_generic_to_shared(smraw);

    const int tid  = threadIdx.x;
    const int wid  = tid >> 5;
    const int lane = tid & 31;
    const int wm   = wid & 3;          // 0..3: m band of 32
    const int wn   = wid >> 2;         // 0..1: n band of 32
    const int bt   = blockIdx.x >> 2;  // 0..63: row tile
    const int nq   = blockIdx.x & 3;   // 0..3: 64-col quarter
    const int R0   = bt * 128;
    const int C0   = nq * 64;

    // A fill: thread -> (m = tid>>1, khalf = tid&1): 16 fp32 -> 2x16B hi + 2x16B lo
    const int am = tid >> 1, ah = tid & 1;
    char* adst_gen = smraw + am * 80 + ah * 32;
    const float* xsrc = x + (size_t)(R0 + am) * DIN + ah * 16;
    // B fill: thread -> (k = tid>>3, unit = tid&7); 16B hi + 16B lo per chunk
    const int bk = tid >> 3, bu = tid & 7;
    const uint32_t bdst = smem + SMEM_B0 + (uint32_t)(bk * 128 + ((bu ^ (bk & 7)) * 16));
    const char* bsrc_h = (const char*)g_Bh + (size_t)bk * 512 + C0 * 2 + bu * 16;
    const char* bsrc_l = (const char*)g_Bl + (size_t)bk * 512 + C0 * 2 + bu * 16;

    float acc[2][4][4];
#pragma unroll
    for (int mt = 0; mt < 2; mt++)
#pragma unroll
        for (int nt = 0; nt < 4; nt++)
#pragma unroll
            for (int e = 0; e < 4; e++) acc[mt][nt][e] = 0.0f;

    // ---- prologue: chunk 0. x loads + A split happen BEFORE the PDL wait ----
    {
        float4 ax[4];
#pragma unroll
        for (int i = 0; i < 4; i++) ax[i] = *(const float4*)(xsrc + i * 4);
        uint32_t hw_[8], lw_[8];
#pragma unroll
        for (int i = 0; i < 4; i++) {
            float h0 = __bfloat162float(__float2bfloat16(ax[i].x));
            float h1 = __bfloat162float(__float2bfloat16(ax[i].y));
            float h2 = __bfloat162float(__float2bfloat16(ax[i].z));
            float h3 = __bfloat162float(__float2bfloat16(ax[i].w));
            hw_[2 * i]     = pack_bf2(h0, h1);
            hw_[2 * i + 1] = pack_bf2(h2, h3);
            lw_[2 * i]     = pack_bf2(ax[i].x - h0, ax[i].y - h1);
            lw_[2 * i + 1] = pack_bf2(ax[i].z - h2, ax[i].w - h3);
        }
        *(uint4*)(adst_gen)             = make_uint4(hw_[0], hw_[1], hw_[2], hw_[3]);
        *(uint4*)(adst_gen + 16)        = make_uint4(hw_[4], hw_[5], hw_[6], hw_[7]);
        *(uint4*)(adst_gen + A_HL)      = make_uint4(lw_[0], lw_[1], lw_[2], lw_[3]);
        *(uint4*)(adst_gen + A_HL + 16) = make_uint4(lw_[4], lw_[5], lw_[6], lw_[7]);

        asm volatile("griddepcontrol.wait;" ::: "memory");   // g_Bh/g_Bl ready

        CPA16(bdst,        bsrc_h);
        CPA16(bdst + B_HL, bsrc_l);
        asm volatile("cp.async.commit_group;\n");
        asm volatile("cp.async.wait_group 0;\n");
    }
    __syncthreads();

    const int l8  = lane & 7;
    const int lb8 = (lane >> 3) & 1;
    const int lhi = (lane >> 4) & 1;

    for (int ct = 0; ct < NCHUNK; ++ct) {
        const int s = ct & 1;
        float4 axn[4];
        if (ct + 1 < NCHUNK) {
            const float* xs2 = xsrc + (ct + 1) * 32;
#pragma unroll
            for (int i = 0; i < 4; i++) axn[i] = *(const float4*)(xs2 + i * 4);
            const uint32_t sb = (uint32_t)((s ^ 1) * B_STAGE);
            const char* bh2 = bsrc_h + (size_t)(ct + 1) * 16384;  // 32 rows * 512 B
            const char* bl2 = bsrc_l + (size_t)(ct + 1) * 16384;
            CPA16(bdst + sb,        bh2);
            CPA16(bdst + sb + B_HL, bl2);
            asm volatile("cp.async.commit_group;\n");
        }

        const uint32_t smA = smem + s * A_STAGE;
        const uint32_t smB = smem + SMEM_B0 + s * B_STAGE;

#pragma unroll
        for (int s2 = 0; s2 < 2; ++s2) {
            uint32_t Af[2][2][4];
#pragma unroll
            for (int mt = 0; mt < 2; ++mt) {
                const int m_loc = wm * 32 + mt * 16 + lb8 * 8 + l8;
                const uint32_t abase = (uint32_t)(m_loc * 80 + (s2 * 2 + lhi) * 16);
                LDSM4(Af[0][mt], smA + abase);
                LDSM4(Af[1][mt], smA + A_HL + abase);
            }
            const int k_loc = s2 * 16 + lb8 * 8 + l8;
            const uint32_t brow = (uint32_t)(k_loc * 128);
            const int kx = k_loc & 7;
#pragma unroll
            for (int np = 0; np < 2; ++np) {
                const int nu = wn * 4 + np * 2 + lhi;
                const uint32_t baddr = brow + (uint32_t)((nu ^ kx) * 16);
                uint32_t Bh[4], Bl[4];
                LDSM4T(Bh, smB + baddr);
                LDSM4T(Bl, smB + B_HL + baddr);
#pragma unroll
                for (int mt = 0; mt < 2; ++mt) {
#pragma unroll
                    for (int e = 0; e < 2; ++e) {
                        float* c = acc[mt][np * 2 + e];
                        MMA_BF16(c, Af[0][mt], Bh[2 * e], Bh[2 * e + 1]);  // hi*hi
                        MMA_BF16(c, Af[0][mt], Bl[2 * e], Bl[2 * e + 1]);  // hi*lo
                        MMA_BF16(c, Af[1][mt], Bh[2 * e], Bh[2 * e + 1]);  // lo*hi
                    }
                }
            }
        }

        if (ct + 1 < NCHUNK) {
            char* ad2 = adst_gen + (s ^ 1) * A_STAGE;
            uint32_t hw_[8], lw_[8];
#pragma unroll
            for (int i = 0; i < 4; i++) {
                float h0 = __bfloat162float(__float2bfloat16(axn[i].x));
                float h1 = __bfloat162float(__float2bfloat16(axn[i].y));
                float h2 = __bfloat162float(__float2bfloat16(axn[i].z));
                float h3 = __bfloat162float(__float2bfloat16(axn[i].w));
                hw_[2 * i]     = pack_bf2(h0, h1);
                hw_[2 * i + 1] = pack_bf2(h2, h3);
                lw_[2 * i]     = pack_bf2(axn[i].x - h0, axn[i].y - h1);
                lw_[2 * i + 1] = pack_bf2(axn[i].z - h2, axn[i].w - h3);
            }
            *(uint4*)(ad2)             = make_uint4(hw_[0], hw_[1], hw_[2], hw_[3]);
            *(uint4*)(ad2 + 16)        = make_uint4(hw_[4], hw_[5], hw_[6], hw_[7]);
            *(uint4*)(ad2 + A_HL)      = make_uint4(lw_[0], lw_[1], lw_[2], lw_[3]);
            *(uint4*)(ad2 + A_HL + 16) = make_uint4(lw_[4], lw_[5], lw_[6], lw_[7]);
            asm volatile("cp.async.wait_group 0;\n");
        }
        __syncthreads();
    }

    // release epi blocks into our tail (their wait still covers our completion)
    asm volatile("griddepcontrol.launch_dependents;");

    const int r_base = R0 + wm * 32 + (lane >> 2);
    const int c_base = C0 + wn * 32 + (lane & 3) * 2;
#pragma unroll
    for (int mt = 0; mt < 2; ++mt) {
#pragma unroll
        for (int nt = 0; nt < 4; ++nt) {
            const int r = r_base + mt * 16;
            const int cc = c_base + nt * 8;
            *(float2*)&g_mid[(size_t)r * NC + cc]       = make_float2(acc[mt][nt][0], acc[mt][nt][1]);
            *(float2*)&g_mid[(size_t)(r + 8) * NC + cc] = make_float2(acc[mt][nt][2], acc[mt][nt][3]);
        }
    }
}

// ---------------- kernel 2: per-row epilogue (no log: e = (p+1e-8)*exp(a-m)) ----------------
__device__ __forceinline__ float smoothstep_f(float v) {
    if (v <= -0.5f) return 0.0f;
    if (v >=  0.5f) return 1.0f;
    return fmaf(-2.0f * v * v, v, fmaf(1.5f, v, 0.5f));
}

__global__ __launch_bounds__(256) void epi_kernel(const float* __restrict__ bz,
                                                  const float* __restrict__ bw,
                                                  const float* __restrict__ P) {
    // Release PDL dependents (y_kernel) immediately; then wait for gemm's grid.
    asm volatile("griddepcontrol.launch_dependents;");
    asm volatile("griddepcontrol.wait;" ::: "memory");

    const int warp = threadIdx.x >> 5;
    const int lane = threadIdx.x & 31;
    const int row  = blockIdx.x * 8 + warp;

    __shared__ float ss[8][120];
    const float* Rm = g_mid + (size_t)row * NC;

    for (int c = lane; c < 120; c += 32)
        ss[warp][c] = smoothstep_f(Rm[c] + bz[c]);
    __syncwarp();

    float A[4], Pv[4];
    int   q[4];
    float m = -3.4028234663852886e38f;
#pragma unroll
    for (int t = 0; t < 4; t++) {
        int qq = lane + 32 * t;
        q[t] = qq;
        int n = qq >> 3, k = qq & 7;
        float p = 1.0f;
#pragma unroll
        for (int l = 0; l < 4; l++) {
            int node = (1 << l) - 1 + (n >> (4 - l));
            int bit  = (n >> (3 - l)) & 1;
            float sv = ss[warp][node * 8 + k];
            p *= bit ? (1.0f - sv) : sv;
        }
        Pv[t] = p;
        A[t]  = Rm[120 + qq] + bw[qq];
        m = fmaxf(m, A[t]);
    }
#pragma unroll
    for (int off = 16; off; off >>= 1)
        m = fmaxf(m, __shfl_xor_sync(0xffffffffu, m, off));

    float wt[16];
#pragma unroll
    for (int l = 0; l < 16; l++) wt[l] = 0.0f;

#pragma unroll
    for (int t = 0; t < 4; t++) {
        // exp(a + log(p+1e-8) - m) == (p+1e-8)*exp(a-m); p<=0 -> excluded (ref: finfo.min)
        float e = (Pv[t] > 0.0f) ? (Pv[t] + 1e-8f) * __expf(A[t] - m) : 0.0f;
        int n = q[t] >> 3, k = q[t] & 7;
        const float4* Pp = (const float4*)(P + ((size_t)(k * 16 + n)) * 16);
#pragma unroll
        for (int u = 0; u < 4; u++) {
            float4 pv = Pp[u];
            wt[4 * u + 0] = fmaf(e, pv.x, wt[4 * u + 0]);
            wt[4 * u + 1] = fmaf(e, pv.y, wt[4 * u + 1]);
            wt[4 * u + 2] = fmaf(e, pv.z, wt[4 * u + 2]);
            wt[4 * u + 3] = fmaf(e, pv.w, wt[4 * u + 3]);
        }
    }

    // value-splitting butterfly: 16 + (8+4+2+1) shuffles; expert = lane & 15
#pragma unroll
    for (int l = 0; l < 16; l++)
        wt[l] += __shfl_xor_sync(0xffffffffu, wt[l], 16);
#pragma unroll
    for (int off = 8; off >= 1; off >>= 1) {
        const bool up = (lane & off) != 0;
#pragma unroll
        for (int i = 0; i < 8; i++) {
            if (i >= off) break;
            float send = up ? wt[i] : wt[i + off];
            float got  = __shfl_xor_sync(0xffffffffu, send, off);
            wt[i] = (up ? wt[i + off] : wt[i]) + got;
        }
    }
    float tot = wt[0];
#pragma unroll
    for (int off = 1; off < 16; off <<= 1)
        tot += __shfl_xor_sync(0xffffffffu, tot, off);

    if (lane < 16)
        g_w[(size_t)row * 16 + lane] = wt[0] / tot;
}

// ---------------- kernel 3: y[b][d] = sum_n f[b][d][n] * w[b][n] (DRAM-bound) ----------------
__global__ __launch_bounds__(256) void y_kernel(const float* __restrict__ f,
                                                float* __restrict__ y) {
    const int b   = blockIdx.x;
    const int tid = threadIdx.x;

    const float4* fb = (const float4*)(f + (size_t)b * 16384);
    // prefetch t=0 (in flight across the dependency wait)
    float4 p0 = fb[tid * 4 + 0];
    float4 p1 = fb[tid * 4 + 1];
    float4 p2 = fb[tid * 4 + 2];
    float4 p3 = fb[tid * 4 + 3];

    asm volatile("griddepcontrol.wait;" ::: "memory");

    const int lane = tid & 31;
    float wv = g_w[(size_t)b * 16 + (lane & 15)];
    float w[16];
#pragma unroll
    for (int n = 0; n < 16; n++) w[n] = __shfl_sync(0xffffffffu, wv, n);

    float* yb = y + (size_t)b * 1024;

    {
        float acc;
        acc = p0.x * w[0];
        acc = fmaf(p0.y, w[1],  acc);
        acc = fmaf(p0.z, w[2],  acc);
        acc = fmaf(p0.w, w[3],  acc);
        acc = fmaf(p1.x, w[4],  acc);
        acc = fmaf(p1.y, w[5],  acc);
        acc = fmaf(p1.z, w[6],  acc);
        acc = fmaf(p1.w, w[7],  acc);
        acc = fmaf(p2.x, w[8],  acc);
        acc = fmaf(p2.y, w[9],  acc);
        acc = fmaf(p2.z, w[10], acc);
        acc = fmaf(p2.w, w[11], acc);
        acc = fmaf(p3.x, w[12], acc);
        acc = fmaf(p3.y, w[13], acc);
        acc = fmaf(p3.z, w[14], acc);
        acc = fmaf(p3.w, w[15], acc);
        yb[tid] = acc;
    }

#pragma unroll
    for (int t = 1; t < 4; t++) {
        int d = tid + t * 256;
        float4 v0 = fb[d * 4 + 0];
        float4 v1 = fb[d * 4 + 1];
        float4 v2 = fb[d * 4 + 2];
        float4 v3 = fb[d * 4 + 3];
        float acc;
        acc = v0.x * w[0];
        acc = fmaf(v0.y, w[1],  acc);
        acc = fmaf(v0.z, w[2],  acc);
        acc = fmaf(v0.w, w[3],  acc);
        acc = fmaf(v1.x, w[4],  acc);
        acc = fmaf(v1.y, w[5],  acc);
        acc = fmaf(v1.z, w[6],  acc);
        acc = fmaf(v1.w, w[7],  acc);
        acc = fmaf(v2.x, w[8],  acc);
        acc = fmaf(v2.y, w[9],  acc);
        acc = fmaf(v2.z, w[10], acc);
        acc = fmaf(v2.w, w[11], acc);
        acc = fmaf(v3.x, w[12], acc);
        acc = fmaf(v3.y, w[13], acc);
        acc = fmaf(v3.z, w[14], acc);
        acc = fmaf(v3.w, w[15], acc);
        yb[d] = acc;
    }
}

// ---------------- launcher: PDL chain on every link ----------------
static void launch_pdl(void* func, dim3 grid, dim3 block, size_t smem,
                       void** args) {
    cudaLaunchConfig_t cfg = {};
    cfg.gridDim  = grid;
    cfg.blockDim = block;
    cfg.dynamicSmemBytes = smem;
    cfg.stream = 0;
    cudaLaunchAttribute attr[1];
    attr[0].id = cudaLaunchAttributeProgrammaticStreamSerialization;
    attr[0].val.programmaticStreamSerializationAllowed = 1;
    cfg.attrs = attr;
    cfg.numAttrs = 1;
    if (cudaLaunchKernelExC(&cfg, func, args) != cudaSuccess) {
        // fallback: plain launch (loses overlap, keeps correctness)
        cudaLaunchKernel(func, grid, block, args, smem, 0);
    }
}

extern "C" void kernel_launch(void* const* d_in, const int* in_sizes, int n_in,
                              void* d_out, int out_size) {
    const float* f  = (const float*)d_in[0];  // (B, 1024, 16)
    const float* x  = (const float*)d_in[1];  // (B, 1024)
    const float* P  = (const float*)d_in[2];  // (8, 16, 16)
    const float* Wz = (const float*)d_in[3];  // (15, 1024, 8)
    const float* bz = (const float*)d_in[4];  // (15, 8)
    const float* Ww = (const float*)d_in[5];  // (16, 1024, 8)
    const float* bw = (const float*)d_in[6];  // (16, 8)
    float* y = (float*)d_out;                 // (B, 1024)

    static bool inited = false;
    if (!inited) {
        cudaFuncSetAttribute(gemm_mma, cudaFuncAttributeMaxDynamicSharedMemorySize, SMEM_TOT);
        inited = true;
    }

    prepack_w<<<DIN, 128>>>(Wz, Ww);

    {   // gemm: starts during prepack (x prefetch), waits before reading g_Bh
        void* args[] = { (void*)&x };
        launch_pdl((void*)gemm_mma, dim3(256), dim3(256), SMEM_TOT, args);
    }
    {   // epi: launches into gemm's store tail, waits for its grid
        void* args[] = { (void*)&bz, (void*)&bw, (void*)&P };
        launch_pdl((void*)epi_kernel, dim3(BB / 8), dim3(256), 0, args);
    }
    {   // y: prefetches f during epi, waits before reading g_w
        void* args[] = { (void*)&f, (void*)&y };
        launch_pdl((void*)y_kernel, dim3(BB), dim3(256), 0, args);
    }
}

// round 17
// speedup vs baseline: 1.0619x; 1.0619x over previous
#include <cuda_runtime.h>
#include <cuda_bf16.h>
#include <cstdint>

// Problem constants (fixed by the dataset)
#define BB   8192
#define DIN  1024
#define NC   256       // padded gating columns (120 z + 128 a + 8 pad)
#define NE   16

// ---------------- scratch (no allocation allowed) ----------------
__device__ uint32_t g_Bh[DIN * NC / 2];   // W hi-split, [k][n] bf16, packed 2/word
__device__ uint32_t g_Bl[DIN * NC / 2];   // W lo-split
__device__ float    g_mid[BB * NC];       // gating result [b][c] (pre-bias)
__device__ float    g_w  [BB * NE];       // final expert weights [b][n]

#define CPA16(dst, src) \
    asm volatile("cp.async.ca.shared.global [%0], [%1], 16;\n" :: "r"(dst), "l"(src))

#define LDSM4(r, addr) \
    asm volatile("ldmatrix.sync.aligned.m8n8.x4.shared.b16 {%0,%1,%2,%3}, [%4];" \
        : "=r"((r)[0]), "=r"((r)[1]), "=r"((r)[2]), "=r"((r)[3]) : "r"(addr))

#define LDSM4T(r, addr) \
    asm volatile("ldmatrix.sync.aligned.m8n8.x4.trans.shared.b16 {%0,%1,%2,%3}, [%4];" \
        : "=r"((r)[0]), "=r"((r)[1]), "=r"((r)[2]), "=r"((r)[3]) : "r"(addr))

#define MMA_BF16(c, a, b0, b1) \
    asm volatile("mma.sync.aligned.m16n8k16.row.col.f32.bf16.bf16.f32 " \
        "{%0,%1,%2,%3}, {%4,%5,%6,%7}, {%8,%9}, {%0,%1,%2,%3};" \
        : "+f"((c)[0]), "+f"((c)[1]), "+f"((c)[2]), "+f"((c)[3]) \
        : "r"((a)[0]), "r"((a)[1]), "r"((a)[2]), "r"((a)[3]), "r"(b0), "r"(b1))

__device__ __forceinline__ uint32_t pack_bf2(float a, float b) {
    __nv_bfloat162 h = __floats2bfloat162_rn(a, b);
    return *(uint32_t*)&h;
}

// ---------------- kernel 0: pack + hi/lo split gating weights ----------------
__global__ void prepack_w(const float* __restrict__ Wz, const float* __restrict__ Ww) {
    // Release gemm (PSS dependent): its pre-wait portion only reads x.
    asm volatile("griddepcontrol.launch_dependents;");
    int k  = blockIdx.x;      // 0..1023
    int n2 = threadIdx.x;     // 0..127 -> cols 2*n2, 2*n2+1
    float v[2];
#pragma unroll
    for (int j = 0; j < 2; j++) {
        int c = 2 * n2 + j;
        float val = 0.0f;
        if (c < 120)       val = Wz[(c >> 3) * (DIN * 8) + k * 8 + (c & 7)];
        else if (c < 248)  { int cc = c - 120; val = Ww[(cc >> 3) * (DIN * 8) + k * 8 + (cc & 7)]; }
        v[j] = val;
    }
    float h0 = __bfloat162float(__float2bfloat16(v[0]));
    float h1 = __bfloat162float(__float2bfloat16(v[1]));
    g_Bh[k * 128 + n2] = pack_bf2(h0, h1);
    g_Bl[k * 128 + n2] = pack_bf2(v[0] - h0, v[1] - h1);
}

// ---------------- kernel 1: gating GEMM via mma.sync bf16, 3-pass hi/lo ----------------
// CTA tile 128 m x 128 n, 128 CTAs (proven R15 shape), but 512 threads:
// warp grid 4(m) x 4(n), warp tile 32x32 -> 4 warps/SMSP to hide LDSM->MMA stalls
// at IDENTICAL per-SM DRAM traffic and smem footprint. acc = 32 regs/thread.
#define BKC      32
#define NCHUNK   (DIN / BKC)
#define A_HL     10240            // 128 * 80
#define A_STAGE  20480
#define B_HL     8192             // 32 k * 256 B
#define B_STAGE  16384
#define SMEM_B0  (2 * A_STAGE)    // 40960
#define SMEM_TOT (2 * A_STAGE + 2 * B_STAGE)   // 73728

__global__ __launch_bounds__(512, 1) void gemm_mma(const float* __restrict__ x) {
    extern __shared__ char smraw[];
    const uint32_t smem = (uint32_t)__cvta_generic_to_shared(smraw);

    const int tid  = threadIdx.x;
    const int wid  = tid >> 5;
    const int lane = tid & 31;
    const int wm   = wid & 3;          // m band of 32
    const int wn   = wid >> 2;         // 0..3: n band of 32
    const int bt   = blockIdx.x >> 1;  // row tile
    const int nh   = blockIdx.x & 1;   // n half of 256
    const int R0   = bt * 128;
    const int C0   = nh * 128;

    // A fill: thread -> (m = tid>>2, quarter = tid&3): 8 fp32 -> 16B hi + 16B lo
    const int am = tid >> 2, aq = tid & 3;
    char* adst_gen = smraw + am * 80 + aq * 16;
    const float* xsrc = x + (size_t)(R0 + am) * DIN + aq * 8;
    // B fill: thread -> (k = tid>>4, unit = tid&15); one 16B unit hi + lo
    const int bk = tid >> 4, bu = tid & 15;
    const uint32_t bdst = smem + SMEM_B0 + (uint32_t)(bk * 256 + ((bu ^ (bk & 7)) * 16));
    const char* bsrc_h = (const char*)g_Bh + (size_t)bk * 512 + C0 * 2 + bu * 16;
    const char* bsrc_l = (const char*)g_Bl + (size_t)bk * 512 + C0 * 2 + bu * 16;

    float acc[2][4][4];
#pragma unroll
    for (int mt = 0; mt < 2; mt++)
#pragma unroll
        for (int nt = 0; nt < 4; nt++)
#pragma unroll
            for (int e = 0; e < 4; e++) acc[mt][nt][e] = 0.0f;

    // ---- prologue: chunk 0. x load + A split happen BEFORE the PDL wait ----
    {
        float4 a0 = *(const float4*)(xsrc);
        float4 a1 = *(const float4*)(xsrc + 4);
        float h0 = __bfloat162float(__float2bfloat16(a0.x));
        float h1 = __bfloat162float(__float2bfloat16(a0.y));
        float h2 = __bfloat162float(__float2bfloat16(a0.z));
        float h3 = __bfloat162float(__float2bfloat16(a0.w));
        float h4 = __bfloat162float(__float2bfloat16(a1.x));
        float h5 = __bfloat162float(__float2bfloat16(a1.y));
        float h6 = __bfloat162float(__float2bfloat16(a1.z));
        float h7 = __bfloat162float(__float2bfloat16(a1.w));
        *(uint4*)(adst_gen) = make_uint4(pack_bf2(h0, h1), pack_bf2(h2, h3),
                                         pack_bf2(h4, h5), pack_bf2(h6, h7));
        *(uint4*)(adst_gen + A_HL) = make_uint4(
            pack_bf2(a0.x - h0, a0.y - h1), pack_bf2(a0.z - h2, a0.w - h3),
            pack_bf2(a1.x - h4, a1.y - h5), pack_bf2(a1.z - h6, a1.w - h7));

        asm volatile("griddepcontrol.wait;" ::: "memory");   // g_Bh/g_Bl ready

        CPA16(bdst,        bsrc_h);
        CPA16(bdst + B_HL, bsrc_l);
        asm volatile("cp.async.commit_group;\n");
        asm volatile("cp.async.wait_group 0;\n");
    }
    __syncthreads();

    const int l8  = lane & 7;
    const int lb8 = (lane >> 3) & 1;
    const int lhi = (lane >> 4) & 1;

    for (int ct = 0; ct < NCHUNK; ++ct) {
        const int s = ct & 1;
        float4 an0, an1;
        if (ct + 1 < NCHUNK) {
            const float* xs2 = xsrc + (ct + 1) * 32;
            an0 = *(const float4*)(xs2);
            an1 = *(const float4*)(xs2 + 4);
            const uint32_t sb = (uint32_t)((s ^ 1) * B_STAGE);
            const char* bh2 = bsrc_h + (size_t)(ct + 1) * 16384;  // 32 rows * 512 B
            const char* bl2 = bsrc_l + (size_t)(ct + 1) * 16384;
            CPA16(bdst + sb,        bh2);
            CPA16(bdst + sb + B_HL, bl2);
            asm volatile("cp.async.commit_group;\n");
        }

        const uint32_t smA = smem + s * A_STAGE;
        const uint32_t smB = smem + SMEM_B0 + s * B_STAGE;

#pragma unroll
        for (int s2 = 0; s2 < 2; ++s2) {
            uint32_t Af[2][2][4];   // [hilo][mtile][4]
#pragma unroll
            for (int mt = 0; mt < 2; ++mt) {
                const int m_loc = wm * 32 + mt * 16 + lb8 * 8 + l8;
                const uint32_t abase = (uint32_t)(m_loc * 80 + (s2 * 2 + lhi) * 16);
                LDSM4(Af[0][mt], smA + abase);
                LDSM4(Af[1][mt], smA + A_HL + abase);
            }
            const int k_loc = s2 * 16 + lb8 * 8 + l8;
            const uint32_t brow = (uint32_t)(k_loc * 256);
            const int kx = k_loc & 7;
#pragma unroll
            for (int np = 0; np < 2; ++np) {
                const int nu = wn * 4 + np * 2 + lhi;    // 0..15
                const uint32_t baddr = brow + (uint32_t)((nu ^ kx) * 16);
                uint32_t Bh[4], Bl[4];
                LDSM4T(Bh, smB + baddr);
                LDSM4T(Bl, smB + B_HL + baddr);
#pragma unroll
                for (int mt = 0; mt < 2; ++mt) {
#pragma unroll
                    for (int e = 0; e < 2; ++e) {
                        float* c = acc[mt][np * 2 + e];
                        MMA_BF16(c, Af[0][mt], Bh[2 * e], Bh[2 * e + 1]);  // hi*hi
                        MMA_BF16(c, Af[0][mt], Bl[2 * e], Bl[2 * e + 1]);  // hi*lo
                        MMA_BF16(c, Af[1][mt], Bh[2 * e], Bh[2 * e + 1]);  // lo*hi
                    }
                }
            }
        }

        if (ct + 1 < NCHUNK) {
            char* ad2 = adst_gen + (s ^ 1) * A_STAGE;
            float h0 = __bfloat162float(__float2bfloat16(an0.x));
            float h1 = __bfloat162float(__float2bfloat16(an0.y));
            float h2 = __bfloat162float(__float2bfloat16(an0.z));
            float h3 = __bfloat162float(__float2bfloat16(an0.w));
            float h4 = __bfloat162float(__float2bfloat16(an1.x));
            float h5 = __bfloat162float(__float2bfloat16(an1.y));
            float h6 = __bfloat162float(__float2bfloat16(an1.z));
            float h7 = __bfloat162float(__float2bfloat16(an1.w));
            *(uint4*)(ad2) = make_uint4(pack_bf2(h0, h1), pack_bf2(h2, h3),
                                        pack_bf2(h4, h5), pack_bf2(h6, h7));
            *(uint4*)(ad2 + A_HL) = make_uint4(
                pack_bf2(an0.x - h0, an0.y - h1), pack_bf2(an0.z - h2, an0.w - h3),
                pack_bf2(an1.x - h4, an1.y - h5), pack_bf2(an1.z - h6, an1.w - h7));
            asm volatile("cp.async.wait_group 0;\n");
        }
        __syncthreads();
    }

    const int r_base = R0 + wm * 32 + (lane >> 2);
    const int c_base = C0 + wn * 32 + (lane & 3) * 2;
#pragma unroll
    for (int mt = 0; mt < 2; ++mt) {
#pragma unroll
        for (int nt = 0; nt < 4; ++nt) {
            const int r = r_base + mt * 16;
            const int cc = c_base + nt * 8;
            *(float2*)&g_mid[(size_t)r * NC + cc]       = make_float2(acc[mt][nt][0], acc[mt][nt][1]);
            *(float2*)&g_mid[(size_t)(r + 8) * NC + cc] = make_float2(acc[mt][nt][2], acc[mt][nt][3]);
        }
    }
}

// ---------------- kernel 2: per-row epilogue (no log: e = (p+1e-8)*exp(a-m)) ----------------
__device__ __forceinline__ float smoothstep_f(float v) {
    if (v <= -0.5f) return 0.0f;
    if (v >=  0.5f) return 1.0f;
    return fmaf(-2.0f * v * v, v, fmaf(1.5f, v, 0.5f));
}

__global__ __launch_bounds__(256) void epi_kernel(const float* __restrict__ bz,
                                                  const float* __restrict__ bw,
                                                  const float* __restrict__ P) {
    // Release PDL dependent (y_kernel): its pre-wait portion only reads f.
    asm volatile("griddepcontrol.launch_dependents;");

    const int warp = threadIdx.x >> 5;
    const int lane = threadIdx.x & 31;
    const int row  = blockIdx.x * 8 + warp;

    __shared__ float ss[8][120];
    const float* Rm = g_mid + (size_t)row * NC;

    for (int c = lane; c < 120; c += 32)
        ss[warp][c] = smoothstep_f(Rm[c] + bz[c]);
    __syncwarp();

    float A[4], Pv[4];
    int   q[4];
    float m = -3.4028234663852886e38f;
#pragma unroll
    for (int t = 0; t < 4; t++) {
        int qq = lane + 32 * t;
        q[t] = qq;
        int n = qq >> 3, k = qq & 7;
        float p = 1.0f;
#pragma unroll
        for (int l = 0; l < 4; l++) {
            int node = (1 << l) - 1 + (n >> (4 - l));
            int bit  = (n >> (3 - l)) & 1;
            float sv = ss[warp][node * 8 + k];
            p *= bit ? (1.0f - sv) : sv;
        }
        Pv[t] = p;
        A[t]  = Rm[120 + qq] + bw[qq];
        m = fmaxf(m, A[t]);
    }
#pragma unroll
    for (int off = 16; off; off >>= 1)
        m = fmaxf(m, __shfl_xor_sync(0xffffffffu, m, off));

    float wt[16];
#pragma unroll
    for (int l = 0; l < 16; l++) wt[l] = 0.0f;

#pragma unroll
    for (int t = 0; t < 4; t++) {
        // exp(a + log(p+1e-8) - m) == (p+1e-8)*exp(a-m); p<=0 -> excluded (ref: finfo.min)
        float e = (Pv[t] > 0.0f) ? (Pv[t] + 1e-8f) * __expf(A[t] - m) : 0.0f;
        int n = q[t] >> 3, k = q[t] & 7;
        const float4* Pp = (const float4*)(P + ((size_t)(k * 16 + n)) * 16);
#pragma unroll
        for (int u = 0; u < 4; u++) {
            float4 pv = Pp[u];
            wt[4 * u + 0] = fmaf(e, pv.x, wt[4 * u + 0]);
            wt[4 * u + 1] = fmaf(e, pv.y, wt[4 * u + 1]);
            wt[4 * u + 2] = fmaf(e, pv.z, wt[4 * u + 2]);
            wt[4 * u + 3] = fmaf(e, pv.w, wt[4 * u + 3]);
        }
    }

    // value-splitting butterfly: 16 + (8+4+2+1) shuffles; expert = lane & 15
#pragma unroll
    for (int l = 0; l < 16; l++)
        wt[l] += __shfl_xor_sync(0xffffffffu, wt[l], 16);
#pragma unroll
    for (int off = 8; off >= 1; off >>= 1) {
        const bool up = (lane & off) != 0;
#pragma unroll
        for (int i = 0; i < 8; i++) {
            if (i >= off) break;
            float send = up ? wt[i] : wt[i + off];
            float got  = __shfl_xor_sync(0xffffffffu, send, off);
            wt[i] = (up ? wt[i + off] : wt[i]) + got;
        }
    }
    float tot = wt[0];
#pragma unroll
    for (int off = 1; off < 16; off <<= 1)
        tot += __shfl_xor_sync(0xffffffffu, tot, off);

    if (lane < 16)
        g_w[(size_t)row * 16 + lane] = wt[0] / tot;
}

// ---------------- kernel 3: y[b][d] = sum_n f[b][d][n] * w[b][n] (DRAM-bound) ----------------
__global__ __launch_bounds__(256) void y_kernel(const float* __restrict__ f,
                                                float* __restrict__ y) {
    const int b   = blockIdx.x;
    const int tid = threadIdx.x;

    const float4* fb = (const float4*)(f + (size_t)b * 16384);
    // prefetch t=0 (in flight across the dependency wait)
    float4 p0 = fb[tid * 4 + 0];
    float4 p1 = fb[tid * 4 + 1];
    float4 p2 = fb[tid * 4 + 2];
    float4 p3 = fb[tid * 4 + 3];

    asm volatile("griddepcontrol.wait;" ::: "memory");

    const int lane = tid & 31;
    float wv = g_w[(size_t)b * 16 + (lane & 15)];
    float w[16];
#pragma unroll
    for (int n = 0; n < 16; n++) w[n] = __shfl_sync(0xffffffffu, wv, n);

    float* yb = y + (size_t)b * 1024;

    {
        float acc;
        acc = p0.x * w[0];
        acc = fmaf(p0.y, w[1],  acc);
        acc = fmaf(p0.z, w[2],  acc);
        acc = fmaf(p0.w, w[3],  acc);
        acc = fmaf(p1.x, w[4],  acc);
        acc = fmaf(p1.y, w[5],  acc);
        acc = fmaf(p1.z, w[6],  acc);
        acc = fmaf(p1.w, w[7],  acc);
        acc = fmaf(p2.x, w[8],  acc);
        acc = fmaf(p2.y, w[9],  acc);
        acc = fmaf(p2.z, w[10], acc);
        acc = fmaf(p2.w, w[11], acc);
        acc = fmaf(p3.x, w[12], acc);
        acc = fmaf(p3.y, w[13], acc);
        acc = fmaf(p3.z, w[14], acc);
        acc = fmaf(p3.w, w[15], acc);
        yb[tid] = acc;
    }

#pragma unroll
    for (int t = 1; t < 4; t++) {
        int d = tid + t * 256;
        float4 v0 = fb[d * 4 + 0];
        float4 v1 = fb[d * 4 + 1];
        float4 v2 = fb[d * 4 + 2];
        float4 v3 = fb[d * 4 + 3];
        float acc;
        acc = v0.x * w[0];
        acc = fmaf(v0.y, w[1],  acc);
        acc = fmaf(v0.z, w[2],  acc);
        acc = fmaf(v0.w, w[3],  acc);
        acc = fmaf(v1.x, w[4],  acc);
        acc = fmaf(v1.y, w[5],  acc);
        acc = fmaf(v1.z, w[6],  acc);
        acc = fmaf(v1.w, w[7],  acc);
        acc = fmaf(v2.x, w[8],  acc);
        acc = fmaf(v2.y, w[9],  acc);
        acc = fmaf(v2.z, w[10], acc);
        acc = fmaf(v2.w, w[11], acc);
        acc = fmaf(v3.x, w[12], acc);
        acc = fmaf(v3.y, w[13], acc);
        acc = fmaf(v3.z, w[14], acc);
        acc = fmaf(v3.w, w[15], acc);
        yb[d] = acc;
    }
}

// ---------------- launcher ----------------
static void launch_pdl(void* func, dim3 grid, dim3 block, size_t smem,
                       void** args) {
    cudaLaunchConfig_t cfg = {};
    cfg.gridDim  = grid;
    cfg.blockDim = block;
    cfg.dynamicSmemBytes = smem;
    cfg.stream = 0;
    cudaLaunchAttribute attr[1];
    attr[0].id = cudaLaunchAttributeProgrammaticStreamSerialization;
    attr[0].val.programmaticStreamSerializationAllowed = 1;
    cfg.attrs = attr;
    cfg.numAttrs = 1;
    if (cudaLaunchKernelExC(&cfg, func, args) != cudaSuccess) {
        // fallback: plain launch (loses overlap, keeps correctness)
        cudaLaunchKernel(func, grid, block, args, smem, 0);
    }
}

extern "C" void kernel_launch(void* const* d_in, const int* in_sizes, int n_in,
                              void* d_out, int out_size) {
    const float* f  = (const float*)d_in[0];  // (B, 1024, 16)
    const float* x  = (const float*)d_in[1];  // (B, 1024)
    const float* P  = (const float*)d_in[2];  // (8, 16, 16)
    const float* Wz = (const float*)d_in[3];  // (15, 1024, 8)
    const float* bz = (const float*)d_in[4];  // (15, 8)
    const float* Ww = (const float*)d_in[5];  // (16, 1024, 8)
    const float* bw = (const float*)d_in[6];  // (16, 8)
    float* y = (float*)d_out;                 // (B, 1024)

    static bool inited = false;
    if (!inited) {
        cudaFuncSetAttribute(gemm_mma, cudaFuncAttributeMaxDynamicSharedMemorySize, SMEM_TOT);
        inited = true;
    }

    prepack_w<<<DIN, 128>>>(Wz, Ww);

    {   // gemm (PSS): starts during prepack, prefetches x chunk-0, waits for g_Bh
        void* args[] = { (void*)&x };
        launch_pdl((void*)gemm_mma, dim3(128), dim3(512), SMEM_TOT, args);
    }
    // epi: plain launch (serialized after gemm); releases y at entry
    epi_kernel<<<BB / 8, 256>>>(bz, bw, P);
    {   // y (PSS): prefetches f during epi, waits before reading g_w
        void* args[] = { (void*)&f, (void*)&y };
        launch_pdl((void*)y_kernel, dim3(BB), dim3(256), 0, args);
    }
}